// round 17
// baseline (speedup 1.0000x reference)
#include <cuda_runtime.h>
#include <cstdint>

// ---------------------------------------------------------------------------
// LocationSlayerArch, round 17:
//  k_fused : 64-h weight tiles (40KB) -> 512 blocks all resident in ONE wave
//            (kills the 1.73-wave crossbar imbalance). Lane owns 2 h in one
//            f32x2 accumulator — per-h operand sequence identical (bit-exact).
//  k_final : W2 split by o-half across blocks (grid 512, 4 blocks/SM) —
//            full-o inner loop per half, per-(t,o) order untouched.
// ---------------------------------------------------------------------------

#define N_BATCH 128
#define T_SEQ   156
#define C_IN    156
#define H_DIM   1024
#define O_DIM   20
#define HB_CNT  8                     // 128-h slabs (g_sb layout)
#define HBG_CNT 16                    // 64-h fused tiles
#define HW      64
#define HB_SZ   128
#define IDX_CAP 160
#define ROW_BYTES 256                 // ws row stride (64 floats)
#define ZROW_OFF ((unsigned)(C_IN * ROW_BYTES))
#define NGRP    8                     // n per fused block (8 warps)
#define WS_BYTES (157 * HW * 4)       // 40192
#define SLOT_BYTES (8 * 512)          // idx double buffers (8 warps)

#define LAM_S  0.90483741803595952f
#define K_PSP  0.27182818284590452f
#define LAM_R  0.36787944117144233f
#define C_REF  -54.365636569180902f
#define C_P16  1.1253517471925912e-07f
#define C_Q16  1.8005627955081459e-06f
#define THETA  10.0f

__device__ __constant__ int c_td[39] = {
    11,25,35,4,18,30,7,2,20,37,29,12,9,33,23,16,1,6,15,21,
    27,34,39,24,17,10,31,38,28,14,3,22,32,8,19,36,5,13,26};

#define NSLAB (2 * N_BATCH * HB_CNT)          // 2048 128-h slabs
__device__ unsigned g_idx[(size_t)2 * N_BATCH * T_SEQ * IDX_CAP];   // 25.6MB
__device__ int      g_cnt[2 * N_BATCH * T_SEQ];
__device__ float    g_w1t[2][C_IN * H_DIM];                         // 1.3MB
__device__ unsigned g_sb[(size_t)NSLAB * T_SEQ * 4];                // 5.1MB

#define LDSV2(a, b, addr) \
    asm volatile("ld.shared.v2.b64 {%0,%1}, [%2];" : "=l"(a), "=l"(b) : "r"(addr))
#define LDS64(a, addr) \
    asm volatile("ld.shared.b64 %0, [%1];" : "=l"(a) : "r"(addr))
#define FADD2(acc, x) \
    asm("add.rn.f32x2 %0, %0, %1;" : "+l"(acc) : "l"(x))
#define LDSV4U(v, addr) \
    asm volatile("ld.shared.v4.u32 {%0,%1,%2,%3}, [%4];" \
                 : "=r"(v.x), "=r"(v.y), "=r"(v.z), "=r"(v.w) : "r"(addr))
#define CPASYNC16(dst, src) \
    asm volatile("cp.async.cg.shared.global [%0], [%1], 16;" :: "r"(dst), "l"(src))

// ---------------------------------------------------------------------------
// K-1: transpose layer-1 weights: g_w1t[path][c*1024 + h] = w[h*156 + c].
// ---------------------------------------------------------------------------
__global__ void __launch_bounds__(256) k_wt(const float* __restrict__ w_main,
                                            const float* __restrict__ w_loc) {
    int i = blockIdx.x * 256 + threadIdx.x;
    if (i >= 2 * C_IN * H_DIM) return;
    int path = i / (C_IN * H_DIM);
    int r = i % (C_IN * H_DIM);
    int c = r / H_DIM, h = r % H_DIM;
    const float* w = path ? w_loc : w_main;
    g_w1t[path][r] = w[(size_t)h * C_IN + c];
}

// ---------------------------------------------------------------------------
// K0: ballot-compacted active-index lists (premultiplied by ROW_BYTES=256).
// ---------------------------------------------------------------------------
__global__ void __launch_bounds__(256) k_bitify(const float* __restrict__ x) {
    extern __shared__ float xs[];                 // [C_IN][T_SEQ]
    int n = blockIdx.x;
    const float* xb = x + (size_t)n * C_IN * T_SEQ;
    for (int i = threadIdx.x; i < C_IN * T_SEQ; i += blockDim.x) xs[i] = xb[i];
    __syncthreads();

    int wrp = threadIdx.x >> 5, lane = threadIdx.x & 31;
    for (int task = wrp; task < 2 * T_SEQ; task += 8) {
        int path = task >= T_SEQ;
        int seq = path ? task - T_SEQ : task;
        unsigned* ob = g_idx + ((size_t)(path * N_BATCH + n) * T_SEQ + seq) * IDX_CAP;

        int pc = 0;
        if (path) {
            int blk = seq / 78, j2 = seq % 78;
            pc = 2 * c_td[j2 >> 1] - 2 + (j2 & 1) + blk * 78;   // PERM[seq]
        }
        int total = 0;
        #pragma unroll
        for (int w = 0; w < 5; w++) {
            int j = w * 32 + lane;
            bool bit = false;
            if (j < C_IN)
                bit = (path ? xs[pc * T_SEQ + j] : xs[j * T_SEQ + seq]) > 0.5f;
            unsigned m = __ballot_sync(0xffffffffu, bit);
            int pos = total + __popc(m & ((1u << lane) - 1u));
            if (bit) ob[pos] = (unsigned)(j * ROW_BYTES);
            total += __popc(m);
        }
        if (lane == 0) {
            while (total & 3) ob[total++] = ZROW_OFF;
            g_cnt[(path * N_BATCH + n) * T_SEQ + seq] = total;
        }
    }
}

// ---------------------------------------------------------------------------
// K1: fused layer-1, 64-h tiles. grid (16 hbg, 16 ng, 2 path) = 512 blocks,
// 256 threads = 8 warps (one n each). Lane owns h = hbg*64 + lane*2 + {0,1}.
// cp.async idx double-buffering per warp. Per-h arithmetic bit-exact.
// ---------------------------------------------------------------------------
__global__ void __launch_bounds__(256, 5) k_fused() {
    extern __shared__ float ws[];   // [157][64] weights + idx slots
    int hbg = blockIdx.x, ng = blockIdx.y, path = blockIdx.z;
    int tid = threadIdx.x;

    const float* wt = g_w1t[path] + hbg * HW;
    for (int i = tid; i < C_IN * HW; i += 256) {
        int c = i >> 6, hl = i & 63;
        ws[i] = wt[c * H_DIM + hl];
    }
    for (int i = tid; i < HW; i += 256) ws[C_IN * HW + i] = 0.0f;
    __syncthreads();

    uint32_t ws32;
    asm("{ .reg .u64 t; cvta.to.shared.u64 t, %1; cvt.u32.u64 %0, t; }"
        : "=r"(ws32) : "l"(ws));

    int wrp = tid >> 5, lane = tid & 31;
    uint32_t base = ws32 + lane * 8;
    uint32_t slot0 = ws32 + WS_BYTES + wrp * 512;   // two 256B buffers
    int n = ng * NGRP + wrp;
    const int seqbase = (path * N_BATCH + n) * T_SEQ;
    int slab = (path * N_BATCH + n) * HB_CNT + (hbg >> 1);
    unsigned* sbout = g_sb + (size_t)slab * (T_SEQ * 4) + (hbg & 1) * 2;

    float A[2] = {0.f, 0.f}, B[2] = {0.f, 0.f};
    float P[2] = {0.f, 0.f}, Q[2] = {0.f, 0.f};
    unsigned hist[2] = {0u, 0u};

    // prologue: stage list for t=0
    {
        const char* src = (const char*)(g_idx + (size_t)seqbase * IDX_CAP);
        if (lane < 16) CPASYNC16(slot0 + lane * 16, src + lane * 16);
        asm volatile("cp.async.commit_group;");
    }
    int cnt_cur = g_cnt[seqbase];

    for (int t = 0; t < T_SEQ; t++) {
        int cnt = cnt_cur;
        const unsigned* ib = g_idx + (size_t)(seqbase + t) * IDX_CAP;
        if (t + 1 < T_SEQ) {
            const char* src = (const char*)(g_idx + (size_t)(seqbase + t + 1) * IDX_CAP);
            if (lane < 16)
                CPASYNC16(slot0 + (((t + 1) & 1) << 8) + lane * 16, src + lane * 16);
            asm volatile("cp.async.commit_group;");
            cnt_cur = g_cnt[seqbase + t + 1];
            asm volatile("cp.async.wait_group 1;" ::: "memory");
        } else {
            asm volatile("cp.async.wait_group 0;" ::: "memory");
        }
        __syncwarp();

        // ---- sparse matvec (frozen per-h order; lane owns 2 h) ----
        uint32_t sl = slot0 + ((t & 1) << 8);
        unsigned long long acc = 0ULL;
        int klim = cnt < 64 ? cnt : 64;
        int k = 0;
        for (; k < klim; k += 4) {
            uint4 v;
            LDSV4U(v, sl + (k << 2));
            unsigned long long a;
            LDS64(a, base + v.x); FADD2(acc, a);
            LDS64(a, base + v.y); FADD2(acc, a);
            LDS64(a, base + v.z); FADD2(acc, a);
            LDS64(a, base + v.w); FADD2(acc, a);
        }
        for (; k < cnt; k += 4) {                    // rare fallback (cnt>64)
            uint4 v = *(const uint4*)(ib + k);
            unsigned long long a;
            LDS64(a, base + v.x); FADD2(acc, a);
            LDS64(a, base + v.y); FADD2(acc, a);
            LDS64(a, base + v.z); FADD2(acc, a);
            LDS64(a, base + v.w); FADD2(acc, a);
        }
        float pre[2];
        uint2 u0 = *reinterpret_cast<uint2*>(&acc);
        pre[0] = __uint_as_float(u0.x); pre[1] = __uint_as_float(u0.y);

        // ---- recurrence for 2 neurons (identical expressions) ----
        unsigned nib = 0u;
        #pragma unroll
        for (int i = 0; i < 2; i++) {
            B[i] = LAM_S * (B[i] + A[i]);
            A[i] = LAM_S * A[i] + pre[i];
            float u  = K_PSP * B[i];
            float um = u + C_REF * Q[i];
            unsigned spk = (um >= THETA) ? 1u : 0u;
            float s = (float)spk;
            float aged = (float)((hist[i] >> 14) & 1u);
            Q[i] = LAM_R * (Q[i] + P[i] + s) - aged * C_Q16;
            P[i] = LAM_R * (P[i] + s)       - aged * C_P16;
            hist[i] = (hist[i] << 1) | spk;
            nib |= spk << i;
        }

        // ---- pack to canonical words (bit j of word = local h) ----
        unsigned v1 = nib | (__shfl_down_sync(0xffffffffu, nib, 1) << 2);
        unsigned v2 = v1  | (__shfl_down_sync(0xffffffffu, v1, 2) << 4);
        unsigned v3 = v2  | (__shfl_down_sync(0xffffffffu, v2, 4) << 8);
        unsigned v4 = v3  | (__shfl_down_sync(0xffffffffu, v3, 8) << 16);
        if ((lane & 15) == 0) sbout[t * 4 + (lane >> 4)] = v4;
    }
}

// ---------------------------------------------------------------------------
// K2: s1 x W2 from bitmasks, W2 split by o-half across blocks.
// grid 512 = (path, n, oh), 256 threads. Thread = one t, all 10 o's of half.
// Per-(t,o) accumulation order identical (o's independent).
// ---------------------------------------------------------------------------
#define W2PAD 12                      // padded row stride (floats), 48B
__global__ void __launch_bounds__(256) k_final(float* __restrict__ out,
                                               const float* __restrict__ wb_main,
                                               const float* __restrict__ wb_loc) {
    extern __shared__ float smem[];
    float* w2s = smem;                     // [1024][12] (10 used), 48KB
    float* v   = smem + H_DIM * W2PAD;     // [156][10]

    int b = blockIdx.x;
    int oh = b & 1, n = (b >> 1) & 127, path = b >> 8;
    int tid = threadIdx.x;
    const float* wb = (path ? wb_loc : wb_main) + (size_t)(oh * 10) * H_DIM;

    for (int i = tid; i < H_DIM * 10; i += 256) {
        int o = i / H_DIM, h = i % H_DIM;
        w2s[h * W2PAD + o] = wb[(size_t)o * H_DIM + h];
    }
    __syncthreads();

    uint32_t w2s32;
    asm("{ .reg .u64 t; cvta.to.shared.u64 t, %1; cvt.u32.u64 %0, t; }"
        : "=r"(w2s32) : "l"(w2s));

    const unsigned* sbb = g_sb + (size_t)(path * N_BATCH + n) * HB_CNT * (T_SEQ * 4);

    for (int t = tid; t < T_SEQ; t += 256) {
        unsigned long long acc[5];
        #pragma unroll
        for (int i = 0; i < 5; i++) acc[i] = 0ULL;
        for (int hb = 0; hb < HB_CNT; hb++) {
            unsigned long long tmp[5];
            #pragma unroll
            for (int i = 0; i < 5; i++) tmp[i] = 0ULL;
            const unsigned* sm = sbb + (size_t)hb * (T_SEQ * 4) + t * 4;
            uint32_t hbbase = w2s32 + (unsigned)(hb * HB_SZ * W2PAD * 4);
            #pragma unroll
            for (int wd = 0; wd < 4; wd++) {
                unsigned m = sm[wd];
                while (m) {
                    int j = __ffs(m) - 1;
                    m &= m - 1u;
                    uint32_t row = hbbase + (unsigned)((wd * 32 + j) * (W2PAD * 4));
                    unsigned long long a, c;
                    LDSV2(a, c, row);
                    FADD2(tmp[0], a); FADD2(tmp[1], c);
                    LDSV2(a, c, row + 16);
                    FADD2(tmp[2], a); FADD2(tmp[3], c);
                    LDS64(a, row + 32);
                    FADD2(tmp[4], a);
                }
            }
            #pragma unroll
            for (int i = 0; i < 5; i++) FADD2(acc[i], tmp[i]);
        }
        float2* vp = (float2*)(v + t * 10);
        #pragma unroll
        for (int i = 0; i < 5; i++) vp[i] = *reinterpret_cast<float2*>(&acc[i]);
    }
    __syncthreads();

    if (tid < 10) {
        int o = oh * 10 + tid;
        float* op = out + ((size_t)n * O_DIM + o) * 312 + path * T_SEQ;
        float A = 0.f, B = 0.f, P = 0.f, Q = 0.f;
        unsigned hist = 0u;
        #pragma unroll 4
        for (int t = 0; t < T_SEQ; t++) {
            float pre = v[t * 10 + tid];
            B = LAM_S * (B + A);
            A = LAM_S * A + pre;
            float u  = K_PSP * B;
            float um = u + C_REF * Q;
            unsigned spk = (um >= THETA) ? 1u : 0u;
            float s = (float)spk;
            float aged = (float)((hist >> 14) & 1u);
            Q = LAM_R * (Q + P + s) - aged * C_Q16;
            P = LAM_R * (P + s)     - aged * C_P16;
            hist = (hist << 1) | spk;
            op[t] = s;
        }
    }
}

// ---------------------------------------------------------------------------
extern "C" void kernel_launch(void* const* d_in, const int* in_sizes, int n_in,
                              void* d_out, int out_size) {
    const float* x   = (const float*)d_in[0];
    const float* w1  = (const float*)d_in[1];
    const float* w2  = (const float*)d_in[2];
    const float* wl1 = (const float*)d_in[3];
    const float* wl2 = (const float*)d_in[4];
    float* out = (float*)d_out;

    const int SM0 = C_IN * T_SEQ * 4;                    // 97344
    const int SM1 = WS_BYTES + SLOT_BYTES;               // 44288
    const int SM2 = (H_DIM * W2PAD + T_SEQ * 10) * 4;    // 55392
    cudaFuncSetAttribute(k_bitify, cudaFuncAttributeMaxDynamicSharedMemorySize, SM0);
    cudaFuncSetAttribute(k_fused,  cudaFuncAttributeMaxDynamicSharedMemorySize, SM1);
    cudaFuncSetAttribute(k_final,  cudaFuncAttributeMaxDynamicSharedMemorySize, SM2);

    k_wt<<<(2 * C_IN * H_DIM + 255) / 256, 256>>>(w1, wl1);
    k_bitify<<<N_BATCH, 256, SM0>>>(x);

    dim3 gf(HBG_CNT, N_BATCH / NGRP, 2);   // 512 blocks, 8 warps each
    k_fused<<<gf, 256, SM1>>>();

    k_final<<<2 * N_BATCH * 2, 256, SM2>>>(out, w2, wl2);
}